// round 16
// baseline (speedup 1.0000x reference)
#include <cuda_runtime.h>
#include <cuda_fp16.h>

#define NN      200000
#define NEDGE   6400000
#define TDIM    6
#define MDIM    10
#define GIN     14
#define GOUT    4
#define CAP     96            // fixed bucket capacity (P[deg>=96] ~ 5e-20)

// ---- static device scratch (no allocation allowed) ----
// Row 0 of g_hx/g_qA/g_qB is an all-zero SENTINEL (BSS zero, never written).
// All stored node indices are shifted by +1; out-of-degree CSR slots are 0
// and therefore gather the sentinel, contributing exactly zero to sums.
__device__ __align__(256) __half g_hx[(NN + 1) * 8]; // x_member fp16, 16B rows
__device__ __align__(256) uint4  g_qA[NN + 1];       // r u8[10] in 16B, buffer A
__device__ __align__(256) uint4  g_qB[NN + 1];       // buffer B
__device__ int   g_cur[NN];                          // invariant: ==0 at entry
__device__ int   g_csr[NN * CAP];                    // slots >= deg stay 0 (sentinel)
__device__ float g_f[MDIM];

// ---- helpers ----
__device__ __forceinline__ float2 h2f(unsigned u) {
    __half2 h = *reinterpret_cast<const __half2*>(&u);
    return __half22float2(h);
}
__device__ __forceinline__ unsigned f2h(float a, float b) {
    __half2 h = __floats2half2_rn(a, b);
    return *reinterpret_cast<unsigned*>(&h);
}

// ---------------------------------------------------------------------------
// build (fused init + scatter); indices stored +1 (0 = sentinel)
// ---------------------------------------------------------------------------
__global__ void k_build(const float* __restrict__ xm,
                        const int* __restrict__ src, const int* __restrict__ dst) {
    int i = blockIdx.x * blockDim.x + threadIdx.x;
    if (i < MDIM) g_f[i] = 0.f;
    if (i < NN) {
        const float* p = xm + (size_t)i * 6;
        uint4 o;
        o.x = f2h(p[0], p[1]);
        o.y = f2h(p[2], p[3]);
        o.z = f2h(p[4], p[5]);
        o.w = 0u;
        *reinterpret_cast<uint4*>(g_hx + (size_t)(i + 1) * 8) = o;
    }
    int e4 = i * 4;
    if (e4 < NEDGE) {
        int4 s = __ldg(reinterpret_cast<const int4*>(src + e4));
        int4 d = __ldg(reinterpret_cast<const int4*>(dst + e4));
        int p0 = atomicAdd(&g_cur[d.x], 1);
        int p1 = atomicAdd(&g_cur[d.y], 1);
        int p2 = atomicAdd(&g_cur[d.z], 1);
        int p3 = atomicAdd(&g_cur[d.w], 1);
        if (p0 < CAP) g_csr[d.x * CAP + p0] = s.x + 1;
        if (p1 < CAP) g_csr[d.y * CAP + p1] = s.y + 1;
        if (p2 < CAP) g_csr[d.z * CAP + p2] = s.z + 1;
        if (p3 < CAP) g_csr[d.w * CAP + p3] = s.w + 1;
    }
}

// ---------------------------------------------------------------------------
// fingerprint accumulation: warp shfl reduce -> shared -> global
// ---------------------------------------------------------------------------
__device__ __forceinline__ void accum_f(float p[MDIM], float* sf, int t) {
#pragma unroll
    for (int m = 0; m < MDIM; m++) {
#pragma unroll
        for (int off = 16; off; off >>= 1)
            p[m] += __shfl_down_sync(0xffffffffu, p[m], off);
    }
    if ((t & 31) == 0) {
#pragma unroll
        for (int m = 0; m < MDIM; m++) atomicAdd(&sf[m], p[m]);
    }
    __syncthreads();
    if (t < MDIM) atomicAdd(&g_f[t], sf[t]);
}

// ---- accumulate helpers (shifted indices; 0 = zero sentinel row) ----
__device__ __forceinline__ void acc6(float* a, int s) {
    uint4 v = __ldg(reinterpret_cast<const uint4*>(g_hx + (size_t)s * 8));
    float2 f;
    f = h2f(v.x); a[0] += f.x; a[1] += f.y;
    f = h2f(v.y); a[2] += f.x; a[3] += f.y;
    f = h2f(v.z); a[4] += f.x; a[5] += f.y;
}
__device__ __forceinline__ void accq(unsigned* a, const uint4* __restrict__ base, int s) {
    uint4 v = __ldg(base + s);
    a[0] = __dp4a(v.x, 0x00000001u, a[0]);
    a[1] = __dp4a(v.x, 0x00000100u, a[1]);
    a[2] = __dp4a(v.x, 0x00010000u, a[2]);
    a[3] = __dp4a(v.x, 0x01000000u, a[3]);
    a[4] = __dp4a(v.y, 0x00000001u, a[4]);
    a[5] = __dp4a(v.y, 0x00000100u, a[5]);
    a[6] = __dp4a(v.y, 0x00010000u, a[6]);
    a[7] = __dp4a(v.y, 0x01000000u, a[7]);
    a[8] = __dp4a(v.z, 0x00000001u, a[8]);
    a[9] = __dp4a(v.z, 0x00000100u, a[9]);
}

// quantize p[10] in (0,1) -> u8, pack into one 16B row
__device__ __forceinline__ void write_qrow(uint4* base, int n, const float* p) {
    unsigned q[MDIM];
#pragma unroll
    for (int m = 0; m < MDIM; m++) q[m] = __float2uint_rn(p[m] * 255.f);
    uint4 o;
    o.x = q[0] | (q[1] << 8) | (q[2] << 16) | (q[3] << 24);
    o.y = q[4] | (q[5] << 8) | (q[6] << 16) | (q[7] << 24);
    o.z = q[8] | (q[9] << 8);
    o.w = 0u;
    base[n] = o;
}

__device__ __forceinline__ void quad_reduce_f(float* a, int cnt) {
#pragma unroll
    for (int m = 0; m < cnt; m++) {
        a[m] += __shfl_xor_sync(0xffffffffu, a[m], 1);
        a[m] += __shfl_xor_sync(0xffffffffu, a[m], 2);
    }
}
__device__ __forceinline__ void quad_reduce_u(unsigned* a, int cnt) {
#pragma unroll
    for (int m = 0; m < cnt; m++) {
        a[m] += __shfl_xor_sync(0xffffffffu, a[m], 1);
        a[m] += __shfl_xor_sync(0xffffffffu, a[m], 2);
    }
}

// quad-shared degree: lane0 of each quad loads, broadcast to quad
__device__ __forceinline__ int quad_degree(int n, int lw) {
    int deg = 0;
    if ((lw & 3) == 0) deg = g_cur[n];
    deg = __shfl_sync(0xffffffffu, deg, lw & ~3);
    return (deg > CAP) ? CAP : deg;
}

// ---------------------------------------------------------------------------
// round 0 (quad-per-node, BT=128; unconditional sentinel-padded chunks; PDL)
// ---------------------------------------------------------------------------
__global__ void __launch_bounds__(128) k_round0(const float* __restrict__ H0,
                                                const float* __restrict__ Wsc) {
    __shared__ float sH[TDIM * MDIM];
    __shared__ float sf[MDIM];
    int t = threadIdx.x;
    if (t < TDIM * MDIM) sH[t] = H0[t];   // input, independent of upstream kernel
    if (t < MDIM) sf[t] = 0.f;
    float w = __ldg(Wsc);
    cudaGridDependencySynchronize();       // wait for k_build results
    __syncthreads();

    int lw = t & 31;
    int lane = t & 3;
    int n = blockIdx.x * 32 + (t >> 2);
    float p[MDIM];
    if (n < NN) {
        float a[TDIM] = {0, 0, 0, 0, 0, 0};
        if (lane == 0) acc6(a, n + 1);             // self term (shifted)
        int deg = quad_degree(n, lw);
        const int4* bkt = reinterpret_cast<const int4*>(g_csr + n * CAP);
        for (int c = lane * 4; c < deg; c += 16) {
            int4 iv = __ldg(bkt + (c >> 2));       // slots >= deg are 0 -> sentinel
            acc6(a, iv.x);
            acc6(a, iv.y);
            acc6(a, iv.z);
            acc6(a, iv.w);
        }
        quad_reduce_f(a, TDIM);

        if (lane == 0) {
#pragma unroll
            for (int m = 0; m < MDIM; m++) {
                float z = 0.f;
#pragma unroll
                for (int j = 0; j < TDIM; j++) z = fmaf(a[j], sH[j * MDIM + m], z);
                p[m] = 1.f / (1.f + __expf(-z));
            }
            write_qrow(g_qA, n + 1, p);
            float mx = -1e30f;
#pragma unroll
            for (int m = 0; m < MDIM; m++) mx = fmaxf(mx, p[m] * w);
            float ssum = 0.f;
#pragma unroll
            for (int m = 0; m < MDIM; m++) { p[m] = __expf(p[m] * w - mx); ssum += p[m]; }
            float inv = 1.f / ssum;
#pragma unroll
            for (int m = 0; m < MDIM; m++) p[m] *= inv;
        } else {
#pragma unroll
            for (int m = 0; m < MDIM; m++) p[m] = 0.f;
        }
    } else {
#pragma unroll
        for (int m = 0; m < MDIM; m++) p[m] = 0.f;
    }
    accum_f(p, sf, t);
}

// ---------------------------------------------------------------------------
// rounds 1..R (quad-per-node, BT=128, u8 rows; unconditional sentinel chunks)
// last!=0: skip dead row write, zero g_cur (restore invariant; sole reader)
// ---------------------------------------------------------------------------
__global__ void __launch_bounds__(128) k_roundR(const float* __restrict__ H,
                                                const float* __restrict__ Wsc,
                                                int flip, int last) {
    __shared__ float sH[MDIM * MDIM];
    __shared__ float sf[MDIM];
    int t = threadIdx.x;
    if (t < MDIM * MDIM) sH[t] = H[t];     // input, independent of upstream kernel
    if (t < MDIM) sf[t] = 0.f;
    float w = __ldg(Wsc);
    cudaGridDependencySynchronize();        // wait for previous round
    __syncthreads();

    const uint4* src = flip ? g_qB : g_qA;
    uint4*       dst = flip ? g_qA : g_qB;

    int lw = t & 31;
    int lane = t & 3;
    int n = blockIdx.x * 32 + (t >> 2);
    float p[MDIM];
    if (n < NN) {
        unsigned a[MDIM] = {0, 0, 0, 0, 0, 0, 0, 0, 0, 0};
        if (lane == 0) accq(a, src, n + 1);        // self term (shifted)
        int deg = quad_degree(n, lw);
        if (last && lane == 0) g_cur[n] = 0;       // safe: quad lane0 was sole reader
        const int4* bkt = reinterpret_cast<const int4*>(g_csr + n * CAP);
        for (int c = lane * 4; c < deg; c += 16) {
            int4 iv = __ldg(bkt + (c >> 2));       // slots >= deg are 0 -> sentinel
            accq(a, src, iv.x);
            accq(a, src, iv.y);
            accq(a, src, iv.z);
            accq(a, src, iv.w);
        }
        quad_reduce_u(a, MDIM);

        if (lane == 0) {
            float af[MDIM];
            const float dq = 1.f / 255.f;
#pragma unroll
            for (int m = 0; m < MDIM; m++) af[m] = (float)a[m] * dq;
#pragma unroll
            for (int m = 0; m < MDIM; m++) {
                float z = 0.f;
#pragma unroll
                for (int j = 0; j < MDIM; j++) z = fmaf(af[j], sH[j * MDIM + m], z);
                p[m] = 1.f / (1.f + __expf(-z));
            }
            if (!last) write_qrow(dst, n + 1, p);
            float mx = -1e30f;
#pragma unroll
            for (int m = 0; m < MDIM; m++) mx = fmaxf(mx, p[m] * w);
            float ssum = 0.f;
#pragma unroll
            for (int m = 0; m < MDIM; m++) { p[m] = __expf(p[m] * w - mx); ssum += p[m]; }
            float inv = 1.f / ssum;
#pragma unroll
            for (int m = 0; m < MDIM; m++) p[m] *= inv;
        } else {
#pragma unroll
            for (int m = 0; m < MDIM; m++) p[m] = 0.f;
        }
    } else {
#pragma unroll
        for (int m = 0; m < MDIM; m++) p[m] = 0.f;
    }
    accum_f(p, sf, t);
}

// ---------------------------------------------------------------------------
// final: group perceptron + merge -> out[3] (PDL: perceptron before sync)
// ---------------------------------------------------------------------------
__global__ void k_final(const float* __restrict__ xg, const float* __restrict__ Wg,
                        const float* __restrict__ Wm, float* __restrict__ out) {
    if (threadIdx.x != 0) { cudaGridDependencySynchronize(); return; }
    float go[GOUT];
#pragma unroll
    for (int j = 0; j < GOUT; j++) {
        float acc = 0.f;
#pragma unroll
        for (int k = 0; k < GIN; k++) acc = fmaf(xg[k], Wg[k * GOUT + j], acc);
        go[j] = acc;
    }
    cudaGridDependencySynchronize();        // g_f complete after last round
#pragma unroll
    for (int o = 0; o < 3; o++) {
        float acc = 0.f;
#pragma unroll
        for (int k = 0; k < MDIM; k++) acc = fmaf(g_f[k], Wm[k * 3 + o], acc);
#pragma unroll
        for (int j = 0; j < GOUT; j++) acc = fmaf(go[j], Wm[(MDIM + j) * 3 + o], acc);
        out[o] = acc;
    }
}

// ---------------------------------------------------------------------------
// host: all launches carry the programmatic-serialization attribute (PDL)
// ---------------------------------------------------------------------------
static void launch_pdl(const void* fn, dim3 grid, dim3 block, void** args) {
    cudaLaunchConfig_t cfg = {};
    cfg.gridDim = grid;
    cfg.blockDim = block;
    cfg.dynamicSmemBytes = 0;
    cfg.stream = 0;
    cudaLaunchAttribute attr[1];
    attr[0].id = cudaLaunchAttributeProgrammaticStreamSerialization;
    attr[0].val.programmaticStreamSerializationAllowed = 1;
    cfg.attrs = attr;
    cfg.numAttrs = 1;
    cudaLaunchKernelExC(&cfg, fn, args);
}

extern "C" void kernel_launch(void* const* d_in, const int* in_sizes, int n_in,
                              void* d_out, int out_size) {
    const float* xm   = (const float*)d_in[0];
    const float* xg   = (const float*)d_in[1];
    const int*   esrc = (const int*)  d_in[2];
    const int*   edst = (const int*)  d_in[3];
    const float* H0   = (const float*)d_in[4];
    const float* Hs   = (const float*)d_in[5];
    const float* Wsc  = (const float*)d_in[6];
    const float* Wg   = (const float*)d_in[7];
    const float* Wm   = (const float*)d_in[8];
    float* out = (float*)d_out;

    dim3 blk256(256), blk128(128);
    dim3 g_build((NEDGE / 4 + 255) / 256);     // 6250 (covers NN too)
    dim3 g_round((NN * 4 + 127) / 128);        // 6250 (quad-per-node, BT=128)
    dim3 g_one(1);
    dim3 b_one(32);

    {   // 0: build
        void* args[] = {(void*)&xm, (void*)&esrc, (void*)&edst};
        launch_pdl((const void*)k_build, g_build, blk256, args);
    }
    {   // 1: round 0
        void* args[] = {(void*)&H0, (void*)&Wsc};
        launch_pdl((const void*)k_round0, g_round, blk128, args);
    }
    const float* h1 = Hs;
    const float* h2 = Hs + MDIM * MDIM;
    const float* h3 = Hs + 2 * MDIM * MDIM;
    const float* w1 = Wsc + 1;
    const float* w2 = Wsc + 2;
    const float* w3 = Wsc + 3;
    int zero = 0, one = 1;
    {   // 2: round 1 (A -> B)
        void* args[] = {(void*)&h1, (void*)&w1, (void*)&zero, (void*)&zero};
        launch_pdl((const void*)k_roundR, g_round, blk128, args);
    }
    {   // 3: round 2 (B -> A)
        void* args[] = {(void*)&h2, (void*)&w2, (void*)&one, (void*)&zero};
        launch_pdl((const void*)k_roundR, g_round, blk128, args);
    }
    {   // 4: round 3 (last; no row write, cleans g_cur)
        void* args[] = {(void*)&h3, (void*)&w3, (void*)&zero, (void*)&one};
        launch_pdl((const void*)k_roundR, g_round, blk128, args);
    }
    {   // 5: final
        void* args[] = {(void*)&xg, (void*)&Wg, (void*)&Wm, (void*)&out};
        launch_pdl((const void*)k_final, g_one, b_one, args);
    }
}

// round 17
// speedup vs baseline: 1.0048x; 1.0048x over previous
#include <cuda_runtime.h>
#include <cuda_fp16.h>

#define NN      200000
#define NEDGE   6400000
#define TDIM    6
#define MDIM    10
#define GIN     14
#define GOUT    4
#define CAP     96            // fixed bucket capacity (P[deg>=96] ~ 5e-20)

// ---- static device scratch (no allocation allowed) ----
__device__ __align__(256) __half g_hx[NN * 8];  // x_member fp16, stride 8 (16B rows)
__device__ __align__(256) uint4  g_qA[NN];      // r quantized u8[10] in 16B, buffer A
__device__ __align__(256) uint4  g_qB[NN];      // buffer B
__device__ int   g_cur[NN];                     // invariant: ==0 at kernel_launch entry
__device__ int   g_csr[NN * CAP];               // fixed buckets; slots >= deg stay 0
__device__ float g_f[MDIM];

// ---- helpers ----
__device__ __forceinline__ float2 h2f(unsigned u) {
    __half2 h = *reinterpret_cast<const __half2*>(&u);
    return __half22float2(h);
}
__device__ __forceinline__ unsigned f2h(float a, float b) {
    __half2 h = __floats2half2_rn(a, b);
    return *reinterpret_cast<unsigned*>(&h);
}

// ---------------------------------------------------------------------------
// build (fused init + scatter): first kernel, no upstream dependency
// ---------------------------------------------------------------------------
__global__ void k_build(const float* __restrict__ xm,
                        const int* __restrict__ src, const int* __restrict__ dst) {
    int i = blockIdx.x * blockDim.x + threadIdx.x;
    if (i < MDIM) g_f[i] = 0.f;
    if (i < NN) {
        const float* p = xm + (size_t)i * 6;
        uint4 o;
        o.x = f2h(p[0], p[1]);
        o.y = f2h(p[2], p[3]);
        o.z = f2h(p[4], p[5]);
        o.w = 0u;
        *reinterpret_cast<uint4*>(g_hx + (size_t)i * 8) = o;
    }
    int e4 = i * 4;
    if (e4 < NEDGE) {
        int4 s = __ldg(reinterpret_cast<const int4*>(src + e4));
        int4 d = __ldg(reinterpret_cast<const int4*>(dst + e4));
        int p0 = atomicAdd(&g_cur[d.x], 1);
        int p1 = atomicAdd(&g_cur[d.y], 1);
        int p2 = atomicAdd(&g_cur[d.z], 1);
        int p3 = atomicAdd(&g_cur[d.w], 1);
        if (p0 < CAP) g_csr[d.x * CAP + p0] = s.x;
        if (p1 < CAP) g_csr[d.y * CAP + p1] = s.y;
        if (p2 < CAP) g_csr[d.z * CAP + p2] = s.z;
        if (p3 < CAP) g_csr[d.w * CAP + p3] = s.w;
    }
}

// ---------------------------------------------------------------------------
// fingerprint accumulation: warp shfl reduce -> shared -> global
// ---------------------------------------------------------------------------
__device__ __forceinline__ void accum_f(float p[MDIM], float* sf, int t) {
#pragma unroll
    for (int m = 0; m < MDIM; m++) {
#pragma unroll
        for (int off = 16; off; off >>= 1)
            p[m] += __shfl_down_sync(0xffffffffu, p[m], off);
    }
    if ((t & 31) == 0) {
#pragma unroll
        for (int m = 0; m < MDIM; m++) atomicAdd(&sf[m], p[m]);
    }
    __syncthreads();
    if (t < MDIM) atomicAdd(&g_f[t], sf[t]);
}

// ---- accumulate helpers ----
__device__ __forceinline__ void acc6(float* a, int s) {
    uint4 v = __ldg(reinterpret_cast<const uint4*>(g_hx + (size_t)s * 8));
    float2 f;
    f = h2f(v.x); a[0] += f.x; a[1] += f.y;
    f = h2f(v.y); a[2] += f.x; a[3] += f.y;
    f = h2f(v.z); a[4] += f.x; a[5] += f.y;
}
__device__ __forceinline__ void accq(unsigned* a, const uint4* __restrict__ base, int s) {
    uint4 v = __ldg(base + s);
    a[0] = __dp4a(v.x, 0x00000001u, a[0]);
    a[1] = __dp4a(v.x, 0x00000100u, a[1]);
    a[2] = __dp4a(v.x, 0x00010000u, a[2]);
    a[3] = __dp4a(v.x, 0x01000000u, a[3]);
    a[4] = __dp4a(v.y, 0x00000001u, a[4]);
    a[5] = __dp4a(v.y, 0x00000100u, a[5]);
    a[6] = __dp4a(v.y, 0x00010000u, a[6]);
    a[7] = __dp4a(v.y, 0x01000000u, a[7]);
    a[8] = __dp4a(v.z, 0x00000001u, a[8]);
    a[9] = __dp4a(v.z, 0x00000100u, a[9]);
}

// quantize p[10] in (0,1) -> u8, pack into one 16B row
__device__ __forceinline__ void write_qrow(uint4* base, int n, const float* p) {
    unsigned q[MDIM];
#pragma unroll
    for (int m = 0; m < MDIM; m++) q[m] = __float2uint_rn(p[m] * 255.f);
    uint4 o;
    o.x = q[0] | (q[1] << 8) | (q[2] << 16) | (q[3] << 24);
    o.y = q[4] | (q[5] << 8) | (q[6] << 16) | (q[7] << 24);
    o.z = q[8] | (q[9] << 8);
    o.w = 0u;
    base[n] = o;
}

__device__ __forceinline__ void quad_reduce_f(float* a, int cnt) {
#pragma unroll
    for (int m = 0; m < cnt; m++) {
        a[m] += __shfl_xor_sync(0xffffffffu, a[m], 1);
        a[m] += __shfl_xor_sync(0xffffffffu, a[m], 2);
    }
}
__device__ __forceinline__ void quad_reduce_u(unsigned* a, int cnt) {
#pragma unroll
    for (int m = 0; m < cnt; m++) {
        a[m] += __shfl_xor_sync(0xffffffffu, a[m], 1);
        a[m] += __shfl_xor_sync(0xffffffffu, a[m], 2);
    }
}

// quad-shared degree: lane0 of each quad loads, broadcast to quad
__device__ __forceinline__ int quad_degree(int n, int lw) {
    int deg = 0;
    if ((lw & 3) == 0) deg = g_cur[n];
    deg = __shfl_sync(0xffffffffu, deg, lw & ~3);
    return (deg > CAP) ? CAP : deg;
}

// ---------------------------------------------------------------------------
// round 0 (quad-per-node, BT=128 for fine retirement granularity; PDL)
// ---------------------------------------------------------------------------
__global__ void __launch_bounds__(128) k_round0(const float* __restrict__ H0,
                                                const float* __restrict__ Wsc) {
    __shared__ float sH[TDIM * MDIM];
    __shared__ float sf[MDIM];
    int t = threadIdx.x;
    if (t < TDIM * MDIM) sH[t] = H0[t];   // input, independent of upstream kernel
    if (t < MDIM) sf[t] = 0.f;
    float w = __ldg(Wsc);
    cudaGridDependencySynchronize();       // wait for k_build results
    __syncthreads();

    int lw = t & 31;
    int lane = t & 3;
    int n = blockIdx.x * 32 + (t >> 2);
    float p[MDIM];
    if (n < NN) {
        float a[TDIM] = {0, 0, 0, 0, 0, 0};
        if (lane == 0) acc6(a, n);                 // self term
        int deg = quad_degree(n, lw);
        const int4* bkt = reinterpret_cast<const int4*>(g_csr + n * CAP);
        for (int c = lane * 4; c < deg; c += 16) {
            int4 iv = __ldg(bkt + (c >> 2));       // 16B-aligned; slots >= deg are 0
            int m = deg - c;
            acc6(a, iv.x);
            if (m > 1) acc6(a, iv.y);
            if (m > 2) acc6(a, iv.z);
            if (m > 3) acc6(a, iv.w);
        }
        quad_reduce_f(a, TDIM);

        if (lane == 0) {
#pragma unroll
            for (int m = 0; m < MDIM; m++) {
                float z = 0.f;
#pragma unroll
                for (int j = 0; j < TDIM; j++) z = fmaf(a[j], sH[j * MDIM + m], z);
                p[m] = 1.f / (1.f + __expf(-z));
            }
            write_qrow(g_qA, n, p);
            float mx = -1e30f;
#pragma unroll
            for (int m = 0; m < MDIM; m++) mx = fmaxf(mx, p[m] * w);
            float ssum = 0.f;
#pragma unroll
            for (int m = 0; m < MDIM; m++) { p[m] = __expf(p[m] * w - mx); ssum += p[m]; }
            float inv = 1.f / ssum;
#pragma unroll
            for (int m = 0; m < MDIM; m++) p[m] *= inv;
        } else {
#pragma unroll
            for (int m = 0; m < MDIM; m++) p[m] = 0.f;
        }
    } else {
#pragma unroll
        for (int m = 0; m < MDIM; m++) p[m] = 0.f;
    }
    accum_f(p, sf, t);
}

// ---------------------------------------------------------------------------
// rounds 1..R (quad-per-node, u8 rows, BT=128), PDL prologue
// last!=0: skip dead row write, zero g_cur (restore invariant; sole reader)
// ---------------------------------------------------------------------------
__global__ void __launch_bounds__(128) k_roundR(const float* __restrict__ H,
                                                const float* __restrict__ Wsc,
                                                int flip, int last) {
    __shared__ float sH[MDIM * MDIM];
    __shared__ float sf[MDIM];
    int t = threadIdx.x;
    if (t < MDIM * MDIM) sH[t] = H[t];     // input, independent of upstream kernel
    if (t < MDIM) sf[t] = 0.f;
    float w = __ldg(Wsc);
    cudaGridDependencySynchronize();        // wait for previous round
    __syncthreads();

    const uint4* src = flip ? g_qB : g_qA;
    uint4*       dst = flip ? g_qA : g_qB;

    int lw = t & 31;
    int lane = t & 3;
    int n = blockIdx.x * 32 + (t >> 2);
    float p[MDIM];
    if (n < NN) {
        unsigned a[MDIM] = {0, 0, 0, 0, 0, 0, 0, 0, 0, 0};
        if (lane == 0) accq(a, src, n);            // self term
        int deg = quad_degree(n, lw);
        if (last && lane == 0) g_cur[n] = 0;       // safe: quad lane0 was sole reader
        const int4* bkt = reinterpret_cast<const int4*>(g_csr + n * CAP);
        for (int c = lane * 4; c < deg; c += 16) {
            int4 iv = __ldg(bkt + (c >> 2));       // 16B-aligned; slots >= deg are 0
            int m = deg - c;
            accq(a, src, iv.x);
            if (m > 1) accq(a, src, iv.y);
            if (m > 2) accq(a, src, iv.z);
            if (m > 3) accq(a, src, iv.w);
        }
        quad_reduce_u(a, MDIM);

        if (lane == 0) {
            float af[MDIM];
            const float dq = 1.f / 255.f;
#pragma unroll
            for (int m = 0; m < MDIM; m++) af[m] = (float)a[m] * dq;
#pragma unroll
            for (int m = 0; m < MDIM; m++) {
                float z = 0.f;
#pragma unroll
                for (int j = 0; j < MDIM; j++) z = fmaf(af[j], sH[j * MDIM + m], z);
                p[m] = 1.f / (1.f + __expf(-z));
            }
            if (!last) write_qrow(dst, n, p);
            float mx = -1e30f;
#pragma unroll
            for (int m = 0; m < MDIM; m++) mx = fmaxf(mx, p[m] * w);
            float ssum = 0.f;
#pragma unroll
            for (int m = 0; m < MDIM; m++) { p[m] = __expf(p[m] * w - mx); ssum += p[m]; }
            float inv = 1.f / ssum;
#pragma unroll
            for (int m = 0; m < MDIM; m++) p[m] *= inv;
        } else {
#pragma unroll
            for (int m = 0; m < MDIM; m++) p[m] = 0.f;
        }
    } else {
#pragma unroll
        for (int m = 0; m < MDIM; m++) p[m] = 0.f;
    }
    accum_f(p, sf, t);
}

// ---------------------------------------------------------------------------
// final: group perceptron + merge -> out[3] (PDL: perceptron before sync)
// ---------------------------------------------------------------------------
__global__ void k_final(const float* __restrict__ xg, const float* __restrict__ Wg,
                        const float* __restrict__ Wm, float* __restrict__ out) {
    if (threadIdx.x != 0) { cudaGridDependencySynchronize(); return; }
    float go[GOUT];
#pragma unroll
    for (int j = 0; j < GOUT; j++) {
        float acc = 0.f;
#pragma unroll
        for (int k = 0; k < GIN; k++) acc = fmaf(xg[k], Wg[k * GOUT + j], acc);
        go[j] = acc;
    }
    cudaGridDependencySynchronize();        // g_f complete after last round
#pragma unroll
    for (int o = 0; o < 3; o++) {
        float acc = 0.f;
#pragma unroll
        for (int k = 0; k < MDIM; k++) acc = fmaf(g_f[k], Wm[k * 3 + o], acc);
#pragma unroll
        for (int j = 0; j < GOUT; j++) acc = fmaf(go[j], Wm[(MDIM + j) * 3 + o], acc);
        out[o] = acc;
    }
}

// ---------------------------------------------------------------------------
// host: all launches carry the programmatic-serialization attribute (PDL)
// ---------------------------------------------------------------------------
static void launch_pdl(const void* fn, dim3 grid, dim3 block, void** args) {
    cudaLaunchConfig_t cfg = {};
    cfg.gridDim = grid;
    cfg.blockDim = block;
    cfg.dynamicSmemBytes = 0;
    cfg.stream = 0;
    cudaLaunchAttribute attr[1];
    attr[0].id = cudaLaunchAttributeProgrammaticStreamSerialization;
    attr[0].val.programmaticStreamSerializationAllowed = 1;
    cfg.attrs = attr;
    cfg.numAttrs = 1;
    cudaLaunchKernelExC(&cfg, fn, args);
}

extern "C" void kernel_launch(void* const* d_in, const int* in_sizes, int n_in,
                              void* d_out, int out_size) {
    const float* xm   = (const float*)d_in[0];
    const float* xg   = (const float*)d_in[1];
    const int*   esrc = (const int*)  d_in[2];
    const int*   edst = (const int*)  d_in[3];
    const float* H0   = (const float*)d_in[4];
    const float* Hs   = (const float*)d_in[5];
    const float* Wsc  = (const float*)d_in[6];
    const float* Wg   = (const float*)d_in[7];
    const float* Wm   = (const float*)d_in[8];
    float* out = (float*)d_out;

    dim3 blk256(256), blk128(128);
    dim3 g_build((NEDGE / 4 + 255) / 256);     // 6250 (covers NN too)
    dim3 g_round((NN * 4 + 127) / 128);        // 6250 (quad-per-node, BT=128)
    dim3 g_one(1);
    dim3 b_one(32);

    {   // 0: build
        void* args[] = {(void*)&xm, (void*)&esrc, (void*)&edst};
        launch_pdl((const void*)k_build, g_build, blk256, args);
    }
    {   // 1: round 0
        void* args[] = {(void*)&H0, (void*)&Wsc};
        launch_pdl((const void*)k_round0, g_round, blk128, args);
    }
    const float* h1 = Hs;
    const float* h2 = Hs + MDIM * MDIM;
    const float* h3 = Hs + 2 * MDIM * MDIM;
    const float* w1 = Wsc + 1;
    const float* w2 = Wsc + 2;
    const float* w3 = Wsc + 3;
    int zero = 0, one = 1;
    {   // 2: round 1 (A -> B)
        void* args[] = {(void*)&h1, (void*)&w1, (void*)&zero, (void*)&zero};
        launch_pdl((const void*)k_roundR, g_round, blk128, args);
    }
    {   // 3: round 2 (B -> A)
        void* args[] = {(void*)&h2, (void*)&w2, (void*)&one, (void*)&zero};
        launch_pdl((const void*)k_roundR, g_round, blk128, args);
    }
    {   // 4: round 3 (last; no row write, cleans g_cur)
        void* args[] = {(void*)&h3, (void*)&w3, (void*)&zero, (void*)&one};
        launch_pdl((const void*)k_roundR, g_round, blk128, args);
    }
    {   // 5: final
        void* args[] = {(void*)&xg, (void*)&Wg, (void*)&Wm, (void*)&out};
        launch_pdl((const void*)k_final, g_one, b_one, args);
    }
}